// round 1
// baseline (speedup 1.0000x reference)
#include <cuda_runtime.h>
#include <math.h>

#define NB 4
#define CIN 256
#define COUT 128
#define HH 64
#define WW 64
#define HO 128
#define WO 128
#define KK9 9
#define CK (CIN*KK9)   // 2304

// ---- scratch (device globals; no allocation) ----
__device__ float g_xn[NB*HH*WW*CIN];        // x in NHWC, 16 MB
__device__ float g_om[NB*27*HH*WW];         // offset conv output, NCHW
__device__ float g_wT[CK*COUT];             // dcn weights (c*9+k, o)
__device__ float g_wT2[16*COUT*COUT];       // deconv weights (tap, i, o)
__device__ float g_y1[NB*HH*WW*COUT];       // dcn output NHWC (pre-BN)
__device__ float g_z[NB*HO*WO*COUT];        // deconv output NHWC (pre-BN)
__device__ float g_part1[256*2*COUT];
__device__ float g_part2[512*2*COUT];
__device__ float g_scale1[COUT], g_shift1[COUT];
__device__ float g_scale2[COUT], g_shift2[COUT];

// ---- 1. transpose x NCHW -> NHWC ----
__global__ void k_transpose_x(const float* __restrict__ x) {
    int idx = blockIdx.x * blockDim.x + threadIdx.x;  // over NB*HH*WW*CIN
    if (idx >= NB*HH*WW*CIN) return;
    int c = idx & (CIN-1);
    int pix = idx >> 8;
    int b = pix >> 12;
    int h = (pix >> 6) & 63;
    int w = pix & 63;
    g_xn[idx] = x[((b*CIN + c)*HH + h)*WW + w];
}

// ---- 2. reorder dcn weights: wT[(c*9+k)*128 + o] = w_dcn[o][c][k] ----
__global__ void k_reorder_wdcn(const float* __restrict__ w_dcn) {
    int idx = blockIdx.x * blockDim.x + threadIdx.x;
    if (idx >= CK*COUT) return;
    int o = idx & 127;
    int ck = idx >> 7;
    g_wT[idx] = w_dcn[o*CK + ck];
}

// ---- 3. reorder deconv weights: wT2[tap*16384 + i*128 + o] = w_up[i][o][ky][kx] ----
__global__ void k_reorder_wup(const float* __restrict__ w_up) {
    int idx = blockIdx.x * blockDim.x + threadIdx.x;
    if (idx >= 16*COUT*COUT) return;
    int tap = idx >> 14;
    int rem = idx & 16383;
    int i = rem >> 7;
    int o = rem & 127;
    g_wT2[idx] = w_up[(i*COUT + o)*16 + tap];
}

// ---- 4. offset conv: om = conv3x3(x, w_off) + b_off   (27 out channels) ----
__global__ void k_offconv(const float* __restrict__ x,
                          const float* __restrict__ w_off,
                          const float* __restrict__ b_off) {
    int co = blockIdx.x;          // 0..26
    int bh = blockIdx.y;          // b*64 + h
    int b = bh >> 6;
    int h = bh & 63;
    int w = threadIdx.x;          // 0..63
    float acc = b_off[co];
    const float* wbase = w_off + co*CIN*9;
    const float* xbase = x + (b*CIN)*HH*WW;
    for (int c = 0; c < CIN; c++) {
        const float* xr = xbase + c*HH*WW;
        const float* wr = wbase + c*9;
        #pragma unroll
        for (int ky = 0; ky < 3; ky++) {
            int yy = h - 1 + ky;
            if (yy < 0 || yy > 63) continue;
            const float* row = xr + yy*WW;
            #pragma unroll
            for (int kx = 0; kx < 3; kx++) {
                int xx = w - 1 + kx;
                if (xx >= 0 && xx <= 63) acc += row[xx] * wr[ky*3 + kx];
            }
        }
    }
    g_om[((b*27 + co)*HH + h)*WW + w] = acc;
}

// ---- 5. modulated deformable conv ----
// block = 256 threads, 4 pixels; out y1 NHWC (pre-BN, with bias)
__global__ void k_dcn(const float* __restrict__ b_dcn) {
    __shared__ float sval[CK*4];      // [ck][p] float4-packed, 36 KB
    __shared__ float swt[36][4];      // corner weights (mask & validity folded)
    __shared__ int   sy0[36], sy1[36], sx0[36], sx1[36];
    __shared__ float sred[COUT*4];

    int tid = threadIdx.x;
    int pixbase = blockIdx.x * 4;
    int b  = pixbase >> 12;
    int h  = (pixbase >> 6) & 63;
    int w0 = pixbase & 63;

    if (tid < 36) {
        int p = tid / 9, k = tid % 9;
        int w = w0 + p;
        int ky = k / 3, kx = k % 3;
        const float* omb = g_om + (b*27)*4096 + h*64 + w;
        float dy = omb[(2*k)*4096];
        float dx = omb[(2*k + 1)*4096];
        float mm = omb[(18 + k)*4096];
        float mask = 1.0f / (1.0f + expf(-mm));
        float ys = (float)(h - 1 + ky) + dy;
        float xs = (float)(w - 1 + kx) + dx;
        float y0f = floorf(ys), x0f = floorf(xs);
        float ly = ys - y0f, lx = xs - x0f;
        int y0 = (int)y0f, x0 = (int)x0f;
        int y1i = y0 + 1, x1i = x0 + 1;
        float vy0 = (y0 >= 0 && y0 < 64) ? 1.0f : 0.0f;
        float vy1 = (y1i >= 0 && y1i < 64) ? 1.0f : 0.0f;
        float vx0 = (x0 >= 0 && x0 < 64) ? 1.0f : 0.0f;
        float vx1 = (x1i >= 0 && x1i < 64) ? 1.0f : 0.0f;
        swt[tid][0] = (1.0f - ly)*(1.0f - lx)*mask*vy0*vx0;
        swt[tid][1] = (1.0f - ly)*lx       *mask*vy0*vx1;
        swt[tid][2] = ly       *(1.0f - lx)*mask*vy1*vx0;
        swt[tid][3] = ly*lx                *mask*vy1*vx1;
        sy0[tid] = min(max(y0, 0), 63);
        sy1[tid] = min(max(y1i, 0), 63);
        sx0[tid] = min(max(x0, 0), 63);
        sx1[tid] = min(max(x1i, 0), 63);
    }
    __syncthreads();

    // gather: c = tid (0..255), 36 (pixel,tap) combos
    {
        int c = tid;
        const float* xb = g_xn + b*HH*WW*CIN;
        #pragma unroll 4
        for (int pk = 0; pk < 36; pk++) {
            int p = pk / 9, k = pk % 9;
            float v00 = xb[(sy0[pk]*64 + sx0[pk])*CIN + c];
            float v01 = xb[(sy0[pk]*64 + sx1[pk])*CIN + c];
            float v10 = xb[(sy1[pk]*64 + sx0[pk])*CIN + c];
            float v11 = xb[(sy1[pk]*64 + sx1[pk])*CIN + c];
            float v = swt[pk][0]*v00 + swt[pk][1]*v01 + swt[pk][2]*v10 + swt[pk][3]*v11;
            sval[(c*9 + k)*4 + p] = v;
        }
    }
    __syncthreads();

    // matvec: o = tid&127, halves split the ck range
    int o = tid & 127;
    int half = tid >> 7;
    float a0 = 0.f, a1 = 0.f, a2 = 0.f, a3 = 0.f;
    const float* wp = g_wT + o;
    const float4* vp = (const float4*)sval;
    int ck0 = half * (CK/2);
    #pragma unroll 4
    for (int ck = ck0; ck < ck0 + CK/2; ck++) {
        float wv = wp[(size_t)ck*COUT];
        float4 v = vp[ck];
        a0 += v.x*wv; a1 += v.y*wv; a2 += v.z*wv; a3 += v.w*wv;
    }
    if (half == 1) {
        sred[o*4+0] = a0; sred[o*4+1] = a1; sred[o*4+2] = a2; sred[o*4+3] = a3;
    }
    __syncthreads();
    if (half == 0) {
        float bo = b_dcn[o];
        a0 += sred[o*4+0] + bo;
        a1 += sred[o*4+1] + bo;
        a2 += sred[o*4+2] + bo;
        a3 += sred[o*4+3] + bo;
        g_y1[(pixbase+0)*COUT + o] = a0;
        g_y1[(pixbase+1)*COUT + o] = a1;
        g_y1[(pixbase+2)*COUT + o] = a2;
        g_y1[(pixbase+3)*COUT + o] = a3;
    }
}

// ---- 6. BN1 partial sums over y1 ----
__global__ void k_bn1_part() {
    int c = threadIdx.x;
    int base = blockIdx.x * 64;      // 256 blocks * 64 pixels = 16384
    float s = 0.f, ss = 0.f;
    for (int i = 0; i < 64; i++) {
        float v = g_y1[(base + i)*COUT + c];
        s += v; ss += v*v;
    }
    g_part1[blockIdx.x*2*COUT + c] = s;
    g_part1[blockIdx.x*2*COUT + COUT + c] = ss;
}

__global__ void k_bn1_fin(const float* __restrict__ gamma,
                          const float* __restrict__ beta) {
    int c = threadIdx.x;
    float s = 0.f, ss = 0.f;
    for (int j = 0; j < 256; j++) {
        s  += g_part1[j*2*COUT + c];
        ss += g_part1[j*2*COUT + COUT + c];
    }
    const float invN = 1.0f / 16384.0f;
    float mean = s * invN;
    float var = ss * invN - mean*mean;
    float rstd = rsqrtf(var + 1e-5f);
    float sc = gamma[c] * rstd;
    g_scale1[c] = sc;
    g_shift1[c] = beta[c] - mean*sc;
}

// ---- 7. transposed conv (reads y1, applies BN1+ReLU on the fly) ----
// block = 256 threads, 8 output pixels in a row
__global__ void k_deconv() {
    __shared__ float sval[4*COUT*2*4];     // [j][i][group][q], 16 KB

    int tid = threadIdx.x;
    int pixbase = blockIdx.x * 8;
    int b   = pixbase >> 14;
    int oy  = (pixbase >> 7) & 127;
    int ox0 = pixbase & 127;
    int py  = (oy + 1) & 1;

    // gather
    {
        int c = tid & 127;
        int sub = tid >> 7;
        #pragma unroll
        for (int it = 0; it < 16; it++) {
            int pair = it*2 + sub;
            int p = pair >> 2;
            int j = pair & 3;
            int jy = j >> 1, jx = j & 1;
            int ox = ox0 + p;
            int px = (ox + 1) & 1;
            int ky = py + jy*2;
            int kx = px + jx*2;
            int ty = oy + 1 - ky;     // = 2*iy
            int tx = ox + 1 - kx;     // = 2*ix
            float v = 0.f;
            if (ty >= 0 && ty <= 126 && tx >= 0 && tx <= 126) {
                int iy = ty >> 1, ix = tx >> 1;
                float raw = g_y1[((b*HH + iy)*WW + ix)*COUT + c];
                v = fmaxf(g_scale1[c]*raw + g_shift1[c], 0.f);
            }
            int group = p & 1, q = p >> 1;
            sval[((j*COUT + c)*2 + group)*4 + q] = v;
        }
    }
    __syncthreads();

    // matvec
    int o = tid & 127;
    int group = tid >> 7;
    int px = (ox0 + group + 1) & 1;
    float a0 = 0.f, a1 = 0.f, a2 = 0.f, a3 = 0.f;
    #pragma unroll
    for (int j = 0; j < 4; j++) {
        int ky = py + (j >> 1)*2;
        int kx = px + (j & 1)*2;
        int tap = ky*4 + kx;
        const float* wp = g_wT2 + tap*COUT*COUT + o;
        const float4* vp = (const float4*)sval + j*COUT*2 + group;
        #pragma unroll 4
        for (int i = 0; i < COUT; i++) {
            float wv = wp[i*COUT];
            float4 v = vp[i*2];
            a0 += v.x*wv; a1 += v.y*wv; a2 += v.z*wv; a3 += v.w*wv;
        }
    }
    float* zp = g_z + (size_t)(pixbase + group)*COUT + o;
    zp[0*COUT]  = a0;
    zp[2*COUT]  = a1;
    zp[4*COUT]  = a2;
    zp[6*COUT]  = a3;
}

// ---- 8. BN2 partial sums over z ----
__global__ void k_bn2_part() {
    int c = threadIdx.x;
    int base = blockIdx.x * 128;     // 512 blocks * 128 pixels = 65536
    float s = 0.f, ss = 0.f;
    for (int i = 0; i < 128; i++) {
        float v = g_z[(size_t)(base + i)*COUT + c];
        s += v; ss += v*v;
    }
    g_part2[blockIdx.x*2*COUT + c] = s;
    g_part2[blockIdx.x*2*COUT + COUT + c] = ss;
}

__global__ void k_bn2_fin(const float* __restrict__ gamma,
                          const float* __restrict__ beta) {
    int c = threadIdx.x;
    float s = 0.f, ss = 0.f;
    for (int j = 0; j < 512; j++) {
        s  += g_part2[j*2*COUT + c];
        ss += g_part2[j*2*COUT + COUT + c];
    }
    const float invN = 1.0f / 65536.0f;
    float mean = s * invN;
    float var = ss * invN - mean*mean;
    float rstd = rsqrtf(var + 1e-5f);
    float sc = gamma[c] * rstd;
    g_scale2[c] = sc;
    g_shift2[c] = beta[c] - mean*sc;
}

// ---- 9. final: BN2 + ReLU + NHWC -> NCHW transpose into d_out ----
__global__ void k_final(float* __restrict__ out) {
    __shared__ float tile[32][33];
    int s0 = blockIdx.x * 32;        // 512 tiles over 16384 spatial
    int c0 = blockIdx.y * 32;        // 4 tiles over 128 channels
    int b  = blockIdx.z;
    #pragma unroll
    for (int i = 0; i < 4; i++) {
        int srow = threadIdx.y + i*8;
        int ch = c0 + threadIdx.x;
        float v = g_z[((size_t)b*16384 + s0 + srow)*COUT + ch];
        tile[srow][threadIdx.x] = fmaxf(g_scale2[ch]*v + g_shift2[ch], 0.f);
    }
    __syncthreads();
    #pragma unroll
    for (int i = 0; i < 4; i++) {
        int crow = threadIdx.y + i*8;
        out[((size_t)b*COUT + c0 + crow)*16384 + s0 + threadIdx.x] = tile[threadIdx.x][crow];
    }
}

extern "C" void kernel_launch(void* const* d_in, const int* in_sizes, int n_in,
                              void* d_out, int out_size) {
    const float* x      = (const float*)d_in[0];
    const float* w_off  = (const float*)d_in[1];
    const float* b_off  = (const float*)d_in[2];
    const float* w_dcn  = (const float*)d_in[3];
    const float* b_dcn  = (const float*)d_in[4];
    const float* gamma1 = (const float*)d_in[5];
    const float* beta1  = (const float*)d_in[6];
    const float* w_up   = (const float*)d_in[7];
    const float* gamma2 = (const float*)d_in[8];
    const float* beta2  = (const float*)d_in[9];
    float* out = (float*)d_out;

    k_transpose_x<<<(NB*HH*WW*CIN + 255)/256, 256>>>(x);
    k_reorder_wdcn<<<(CK*COUT + 255)/256, 256>>>(w_dcn);
    k_reorder_wup<<<(16*COUT*COUT + 255)/256, 256>>>(w_up);
    k_offconv<<<dim3(27, NB*HH), 64>>>(x, w_off, b_off);
    k_dcn<<<NB*HH*WW/4, 256>>>(b_dcn);
    k_bn1_part<<<256, COUT>>>();
    k_bn1_fin<<<1, COUT>>>(gamma1, beta1);
    k_deconv<<<NB*HO*WO/8, 256>>>();
    k_bn2_part<<<512, COUT>>>();
    k_bn2_fin<<<1, COUT>>>(gamma2, beta2);
    k_final<<<dim3(512, 4, NB), dim3(32, 8)>>>(out);
}

// round 6
// speedup vs baseline: 1.2771x; 1.2771x over previous
#include <cuda_runtime.h>
#include <math.h>

#define NB 4
#define CIN 256
#define COUT 128
#define HH 64
#define WW 64
#define HO 128
#define WO 128
#define KK9 9
#define CK (CIN*KK9)   // 2304

// ---- scratch (device globals; no allocation) ----
__device__ float g_xn[NB*HH*WW*CIN];        // x in NHWC, 16 MB
__device__ float g_om[NB*27*HH*WW];         // offset conv output, NCHW
__device__ float g_wT[CK*COUT];             // dcn weights (c*9+k, o)
__device__ float g_wTo[CK*32];              // offconv weights (c*9+k, co) padded 27->32
__device__ float g_wT2[16*COUT*COUT];       // deconv weights (tap, i, o)
__device__ float g_y1[NB*HH*WW*COUT];       // dcn output NHWC (pre-BN)
__device__ float g_z[NB*HO*WO*COUT];        // deconv output NHWC (pre-BN)
__device__ float g_part1[256*2*COUT];
__device__ float g_part2[512*2*COUT];
__device__ float g_scale1[COUT], g_shift1[COUT];
__device__ float g_scale2[COUT], g_shift2[COUT];

// ---- 1. transpose x NCHW -> NHWC ----
__global__ void k_transpose_x(const float* __restrict__ x) {
    int idx = blockIdx.x * blockDim.x + threadIdx.x;  // over NB*HH*WW*CIN
    if (idx >= NB*HH*WW*CIN) return;
    int c = idx & (CIN-1);
    int pix = idx >> 8;
    int b = pix >> 12;
    int h = (pix >> 6) & 63;
    int w = pix & 63;
    g_xn[idx] = x[((b*CIN + c)*HH + h)*WW + w];
}

// ---- 2. reorder dcn weights: wT[(c*9+k)*128 + o] = w_dcn[o][c][k] ----
__global__ void k_reorder_wdcn(const float* __restrict__ w_dcn) {
    int idx = blockIdx.x * blockDim.x + threadIdx.x;
    if (idx >= CK*COUT) return;
    int o = idx & 127;
    int ck = idx >> 7;
    g_wT[idx] = w_dcn[o*CK + ck];
}

// ---- 2b. reorder offset-conv weights: wTo[ck*32 + co] = w_off[co][ck], pad ----
__global__ void k_reorder_woff(const float* __restrict__ w_off) {
    int idx = blockIdx.x * blockDim.x + threadIdx.x;
    if (idx >= CK*32) return;
    int co = idx & 31;
    int ck = idx >> 5;
    g_wTo[idx] = (co < 27) ? w_off[co*CK + ck] : 0.0f;
}

// ---- 3. reorder deconv weights: wT2[tap*16384 + i*128 + o] = w_up[i][o][ky][kx] ----
__global__ void k_reorder_wup(const float* __restrict__ w_up) {
    int idx = blockIdx.x * blockDim.x + threadIdx.x;
    if (idx >= 16*COUT*COUT) return;
    int tap = idx >> 14;
    int rem = idx & 16383;
    int i = rem >> 7;
    int o = rem & 127;
    g_wT2[idx] = w_up[(i*COUT + o)*16 + tap];
}

// ---- 4. offset conv, shared-tile version ----
// block = 256 threads, 8 pixels in a row. Tile: 3 rows x 10 cols x 256 ch.
__global__ void k_offconv(const float* __restrict__ b_off) {
    __shared__ float tile[CIN*30];        // tile[c*30 + r*10 + col], 30 KB
    __shared__ float sred[32*8*8];        // [co][slice][p], 8 KB

    int tid = threadIdx.x;
    int pixbase = blockIdx.x * 8;
    int b  = pixbase >> 12;
    int h  = (pixbase >> 6) & 63;
    int w0 = pixbase & 63;

    // gather: thread = channel
    {
        int c = tid;
        const float* xb = g_xn + (size_t)b*HH*WW*CIN;
        #pragma unroll
        for (int r = 0; r < 3; r++) {
            int yy = h - 1 + r;
            bool vy = (yy >= 0 && yy < HH);
            #pragma unroll
            for (int col = 0; col < 10; col++) {
                int xx = w0 - 1 + col;
                float v = 0.f;
                if (vy && xx >= 0 && xx < WW) v = xb[(yy*WW + xx)*CIN + c];
                tile[c*30 + r*10 + col] = v;
            }
        }
    }
    __syncthreads();

    // matvec: o = tid&31 (27 valid co), slice = tid>>5 splits channels
    {
        int o = tid & 31;
        int slice = tid >> 5;
        float acc[8] = {0,0,0,0,0,0,0,0};
        for (int cl = 0; cl < 32; cl++) {
            int c = slice*32 + cl;
            const float* tc = tile + c*30;
            float t[30];
            #pragma unroll
            for (int j = 0; j < 30; j++) t[j] = tc[j];
            const float* wp = g_wTo + (size_t)(c*9)*32 + o;
            #pragma unroll
            for (int ky = 0; ky < 3; ky++) {
                #pragma unroll
                for (int kx = 0; kx < 3; kx++) {
                    float wv = wp[(ky*3 + kx)*32];
                    #pragma unroll
                    for (int p = 0; p < 8; p++)
                        acc[p] += t[ky*10 + kx + p] * wv;
                }
            }
        }
        #pragma unroll
        for (int p = 0; p < 8; p++)
            sred[(o*8 + slice)*8 + p] = acc[p];
    }
    __syncthreads();

    // reduce 8 slices, add bias, write
    if (tid < 27*8) {
        int co = tid >> 3;
        int p  = tid & 7;
        float s = b_off[co];
        #pragma unroll
        for (int sl = 0; sl < 8; sl++)
            s += sred[(co*8 + sl)*8 + p];
        g_om[((b*27 + co)*HH + h)*WW + w0 + p] = s;
    }
}

// ---- 5. modulated deformable conv ----
// block = 256 threads, 4 pixels; out y1 NHWC (pre-BN, with bias)
__global__ void k_dcn(const float* __restrict__ b_dcn) {
    __shared__ float sval[CK*4];      // [ck][p] float4-packed, 36 KB
    __shared__ float swt[36][4];      // corner weights (mask & validity folded)
    __shared__ int   sy0[36], sy1[36], sx0[36], sx1[36];
    __shared__ float sred[COUT*4];

    int tid = threadIdx.x;
    int pixbase = blockIdx.x * 4;
    int b  = pixbase >> 12;
    int h  = (pixbase >> 6) & 63;
    int w0 = pixbase & 63;

    if (tid < 36) {
        int p = tid / 9, k = tid % 9;
        int w = w0 + p;
        int ky = k / 3, kx = k % 3;
        const float* omb = g_om + (b*27)*4096 + h*64 + w;
        float dy = omb[(2*k)*4096];
        float dx = omb[(2*k + 1)*4096];
        float mm = omb[(18 + k)*4096];
        float mask = 1.0f / (1.0f + expf(-mm));
        float ys = (float)(h - 1 + ky) + dy;
        float xs = (float)(w - 1 + kx) + dx;
        float y0f = floorf(ys), x0f = floorf(xs);
        float ly = ys - y0f, lx = xs - x0f;
        int y0 = (int)y0f, x0 = (int)x0f;
        int y1i = y0 + 1, x1i = x0 + 1;
        float vy0 = (y0 >= 0 && y0 < 64) ? 1.0f : 0.0f;
        float vy1 = (y1i >= 0 && y1i < 64) ? 1.0f : 0.0f;
        float vx0 = (x0 >= 0 && x0 < 64) ? 1.0f : 0.0f;
        float vx1 = (x1i >= 0 && x1i < 64) ? 1.0f : 0.0f;
        swt[tid][0] = (1.0f - ly)*(1.0f - lx)*mask*vy0*vx0;
        swt[tid][1] = (1.0f - ly)*lx       *mask*vy0*vx1;
        swt[tid][2] = ly       *(1.0f - lx)*mask*vy1*vx0;
        swt[tid][3] = ly*lx                *mask*vy1*vx1;
        sy0[tid] = min(max(y0, 0), 63);
        sy1[tid] = min(max(y1i, 0), 63);
        sx0[tid] = min(max(x0, 0), 63);
        sx1[tid] = min(max(x1i, 0), 63);
    }
    __syncthreads();

    // gather: c = tid (0..255), 36 (pixel,tap) combos
    {
        int c = tid;
        const float* xb = g_xn + b*HH*WW*CIN;
        #pragma unroll 4
        for (int pk = 0; pk < 36; pk++) {
            int p = pk / 9, k = pk % 9;
            float v00 = xb[(sy0[pk]*64 + sx0[pk])*CIN + c];
            float v01 = xb[(sy0[pk]*64 + sx1[pk])*CIN + c];
            float v10 = xb[(sy1[pk]*64 + sx0[pk])*CIN + c];
            float v11 = xb[(sy1[pk]*64 + sx1[pk])*CIN + c];
            float v = swt[pk][0]*v00 + swt[pk][1]*v01 + swt[pk][2]*v10 + swt[pk][3]*v11;
            sval[(c*9 + k)*4 + p] = v;
        }
    }
    __syncthreads();

    // matvec: o = tid&127, halves split the ck range
    int o = tid & 127;
    int half = tid >> 7;
    float a0 = 0.f, a1 = 0.f, a2 = 0.f, a3 = 0.f;
    const float* wp = g_wT + o;
    const float4* vp = (const float4*)sval;
    int ck0 = half * (CK/2);
    #pragma unroll 4
    for (int ck = ck0; ck < ck0 + CK/2; ck++) {
        float wv = wp[(size_t)ck*COUT];
        float4 v = vp[ck];
        a0 += v.x*wv; a1 += v.y*wv; a2 += v.z*wv; a3 += v.w*wv;
    }
    if (half == 1) {
        sred[o*4+0] = a0; sred[o*4+1] = a1; sred[o*4+2] = a2; sred[o*4+3] = a3;
    }
    __syncthreads();
    if (half == 0) {
        float bo = b_dcn[o];
        a0 += sred[o*4+0] + bo;
        a1 += sred[o*4+1] + bo;
        a2 += sred[o*4+2] + bo;
        a3 += sred[o*4+3] + bo;
        g_y1[(pixbase+0)*COUT + o] = a0;
        g_y1[(pixbase+1)*COUT + o] = a1;
        g_y1[(pixbase+2)*COUT + o] = a2;
        g_y1[(pixbase+3)*COUT + o] = a3;
    }
}

// ---- 6. BN1 partial sums over y1 ----
__global__ void k_bn1_part() {
    int c = threadIdx.x;
    int base = blockIdx.x * 64;      // 256 blocks * 64 pixels = 16384
    float s = 0.f, ss = 0.f;
    for (int i = 0; i < 64; i++) {
        float v = g_y1[(base + i)*COUT + c];
        s += v; ss += v*v;
    }
    g_part1[blockIdx.x*2*COUT + c] = s;
    g_part1[blockIdx.x*2*COUT + COUT + c] = ss;
}

__global__ void k_bn1_fin(const float* __restrict__ gamma,
                          const float* __restrict__ beta) {
    int c = threadIdx.x;
    float s = 0.f, ss = 0.f;
    for (int j = 0; j < 256; j++) {
        s  += g_part1[j*2*COUT + c];
        ss += g_part1[j*2*COUT + COUT + c];
    }
    const float invN = 1.0f / 16384.0f;
    float mean = s * invN;
    float var = ss * invN - mean*mean;
    float rstd = rsqrtf(var + 1e-5f);
    float sc = gamma[c] * rstd;
    g_scale1[c] = sc;
    g_shift1[c] = beta[c] - mean*sc;
}

// ---- 7. transposed conv (reads y1, applies BN1+ReLU on the fly) ----
// block = 256 threads, 8 output pixels in a row
__global__ void k_deconv() {
    __shared__ float sval[4*COUT*2*4];     // [j][i][group][q], 16 KB

    int tid = threadIdx.x;
    int pixbase = blockIdx.x * 8;
    int b   = pixbase >> 14;
    int oy  = (pixbase >> 7) & 127;
    int ox0 = pixbase & 127;
    int py  = (oy + 1) & 1;

    // gather
    {
        int c = tid & 127;
        int sub = tid >> 7;
        #pragma unroll
        for (int it = 0; it < 16; it++) {
            int pair = it*2 + sub;
            int p = pair >> 2;
            int j = pair & 3;
            int jy = j >> 1, jx = j & 1;
            int ox = ox0 + p;
            int px = (ox + 1) & 1;
            int ky = py + jy*2;
            int kx = px + jx*2;
            int ty = oy + 1 - ky;     // = 2*iy
            int tx = ox + 1 - kx;     // = 2*ix
            float v = 0.f;
            if (ty >= 0 && ty <= 126 && tx >= 0 && tx <= 126) {
                int iy = ty >> 1, ix = tx >> 1;
                float raw = g_y1[((b*HH + iy)*WW + ix)*COUT + c];
                v = fmaxf(g_scale1[c]*raw + g_shift1[c], 0.f);
            }
            int group = p & 1, q = p >> 1;
            sval[((j*COUT + c)*2 + group)*4 + q] = v;
        }
    }
    __syncthreads();

    // matvec
    int o = tid & 127;
    int group = tid >> 7;
    int px = (ox0 + group + 1) & 1;
    float a0 = 0.f, a1 = 0.f, a2 = 0.f, a3 = 0.f;
    #pragma unroll
    for (int j = 0; j < 4; j++) {
        int ky = py + (j >> 1)*2;
        int kx = px + (j & 1)*2;
        int tap = ky*4 + kx;
        const float* wp = g_wT2 + tap*COUT*COUT + o;
        const float4* vp = (const float4*)sval + j*COUT*2 + group;
        #pragma unroll 4
        for (int i = 0; i < COUT; i++) {
            float wv = wp[i*COUT];
            float4 v = vp[i*2];
            a0 += v.x*wv; a1 += v.y*wv; a2 += v.z*wv; a3 += v.w*wv;
        }
    }
    float* zp = g_z + (size_t)(pixbase + group)*COUT + o;
    zp[0*COUT]  = a0;
    zp[2*COUT]  = a1;
    zp[4*COUT]  = a2;
    zp[6*COUT]  = a3;
}

// ---- 8. BN2 partial sums over z ----
__global__ void k_bn2_part() {
    int c = threadIdx.x;
    int base = blockIdx.x * 128;     // 512 blocks * 128 pixels = 65536
    float s = 0.f, ss = 0.f;
    for (int i = 0; i < 128; i++) {
        float v = g_z[(size_t)(base + i)*COUT + c];
        s += v; ss += v*v;
    }
    g_part2[blockIdx.x*2*COUT + c] = s;
    g_part2[blockIdx.x*2*COUT + COUT + c] = ss;
}

__global__ void k_bn2_fin(const float* __restrict__ gamma,
                          const float* __restrict__ beta) {
    int c = threadIdx.x;
    float s = 0.f, ss = 0.f;
    for (int j = 0; j < 512; j++) {
        s  += g_part2[j*2*COUT + c];
        ss += g_part2[j*2*COUT + COUT + c];
    }
    const float invN = 1.0f / 65536.0f;
    float mean = s * invN;
    float var = ss * invN - mean*mean;
    float rstd = rsqrtf(var + 1e-5f);
    float sc = gamma[c] * rstd;
    g_scale2[c] = sc;
    g_shift2[c] = beta[c] - mean*sc;
}

// ---- 9. final: BN2 + ReLU + NHWC -> NCHW transpose into d_out ----
__global__ void k_final(float* __restrict__ out) {
    __shared__ float tile[32][33];
    int s0 = blockIdx.x * 32;        // 512 tiles over 16384 spatial
    int c0 = blockIdx.y * 32;        // 4 tiles over 128 channels
    int b  = blockIdx.z;
    #pragma unroll
    for (int i = 0; i < 4; i++) {
        int srow = threadIdx.y + i*8;
        int ch = c0 + threadIdx.x;
        float v = g_z[((size_t)b*16384 + s0 + srow)*COUT + ch];
        tile[srow][threadIdx.x] = fmaxf(g_scale2[ch]*v + g_shift2[ch], 0.f);
    }
    __syncthreads();
    #pragma unroll
    for (int i = 0; i < 4; i++) {
        int crow = threadIdx.y + i*8;
        out[((size_t)b*COUT + c0 + crow)*16384 + s0 + threadIdx.x] = tile[threadIdx.x][crow];
    }
}

extern "C" void kernel_launch(void* const* d_in, const int* in_sizes, int n_in,
                              void* d_out, int out_size) {
    const float* x      = (const float*)d_in[0];
    const float* w_off  = (const float*)d_in[1];
    const float* b_off  = (const float*)d_in[2];
    const float* w_dcn  = (const float*)d_in[3];
    const float* b_dcn  = (const float*)d_in[4];
    const float* gamma1 = (const float*)d_in[5];
    const float* beta1  = (const float*)d_in[6];
    const float* w_up   = (const float*)d_in[7];
    const float* gamma2 = (const float*)d_in[8];
    const float* beta2  = (const float*)d_in[9];
    float* out = (float*)d_out;

    k_transpose_x<<<(NB*HH*WW*CIN + 255)/256, 256>>>(x);
    k_reorder_wdcn<<<(CK*COUT + 255)/256, 256>>>(w_dcn);
    k_reorder_woff<<<(CK*32 + 255)/256, 256>>>(w_off);
    k_reorder_wup<<<(16*COUT*COUT + 255)/256, 256>>>(w_up);
    k_offconv<<<NB*HH*WW/8, 256>>>(b_off);
    k_dcn<<<NB*HH*WW/4, 256>>>(b_dcn);
    k_bn1_part<<<256, COUT>>>();
    k_bn1_fin<<<1, COUT>>>(gamma1, beta1);
    k_deconv<<<NB*HO*WO/8, 256>>>();
    k_bn2_part<<<512, COUT>>>();
    k_bn2_fin<<<1, COUT>>>(gamma2, beta2);
    k_final<<<dim3(512, 4, NB), dim3(32, 8)>>>(out);
}